// round 2
// baseline (speedup 1.0000x reference)
#include <cuda_runtime.h>
#include <math.h>

#define NN 20000
#define EE 320000
#define DIM 128
#define GDIM 512          // HEADS * DIM
#define NHEADS 4
#define NB 16
#define NACT 10
#define NEG_SLOPE 0.2f

// ---------------- scratch (static __device__, no allocs) ----------------
static __device__ int   d_deg[NN];
static __device__ int   d_rowptr[NN + 1];
static __device__ int   d_wptr[NN];
static __device__ int   d_csrsrc[EE];
static __device__ float d_nm[NN * DIM];          // neighbor mean
static __device__ float d_h[NN * DIM];           // SAGE output
static __device__ float d_g[(size_t)NN * GDIM];  // GAT transformed feats
static __device__ float d_as[NN * NHEADS];
static __device__ float d_ad[NN * NHEADS];
static __device__ float d_h2[NN * DIM];          // GAT output
static __device__ float d_pool[NB * DIM];
static __device__ float d_pcnt[NB];

// ---------------- kernels ----------------

__global__ void k_zero() {
    int i = blockIdx.x * blockDim.x + threadIdx.x;
    if (i < NN) { d_deg[i] = 0; d_wptr[i] = 0; }
    if (i < NB * DIM) d_pool[i] = 0.f;
    if (i < NB) d_pcnt[i] = 0.f;
}

__global__ void k_count(const int* __restrict__ ei) {
    int i = blockIdx.x * blockDim.x + threadIdx.x;
    if (i < EE) atomicAdd(&d_deg[ei[EE + i]], 1);
}

// single-block inclusive scan -> exclusive rowptr
__global__ void k_scan() {
    __shared__ int sh[1024];
    __shared__ int carry;
    int tid = threadIdx.x;
    if (tid == 0) { carry = 0; d_rowptr[0] = 0; }
    __syncthreads();
    for (int base = 0; base < NN; base += 1024) {
        int i = base + tid;
        int v = (i < NN) ? d_deg[i] : 0;
        sh[tid] = v;
        __syncthreads();
        for (int off = 1; off < 1024; off <<= 1) {
            int t = (tid >= off) ? sh[tid - off] : 0;
            __syncthreads();
            sh[tid] += t;
            __syncthreads();
        }
        if (i < NN) d_rowptr[i + 1] = carry + sh[tid];
        __syncthreads();
        if (tid == 1023) carry += sh[1023];
        __syncthreads();
    }
}

__global__ void k_scatter(const int* __restrict__ ei) {
    int i = blockIdx.x * blockDim.x + threadIdx.x;
    if (i < EE) {
        int s = ei[i];
        int t = ei[EE + i];
        int pos = d_rowptr[t] + atomicAdd(&d_wptr[t], 1);
        d_csrsrc[pos] = s;
    }
}

// neighbor mean: one block per node, 128 threads (one per channel)
__global__ void k_sage_agg(const float* __restrict__ x) {
    int n = blockIdx.x;
    int tid = threadIdx.x;
    int beg = d_rowptr[n], end = d_rowptr[n + 1];
    float acc = 0.f;
    for (int j = beg; j < end; j++) {
        int s = d_csrsrc[j];
        acc += x[(size_t)s * DIM + tid];
    }
    float deg = (float)(end - beg);
    d_nm[n * DIM + tid] = acc / fmaxf(deg, 1.f);
}

// h = elu(nm@W_l + x@W_r + b) ; 4 nodes per block for W reuse
__global__ void k_sage_lin(const float* __restrict__ x,
                           const float* __restrict__ Wl,
                           const float* __restrict__ Wr,
                           const float* __restrict__ bs) {
    __shared__ float sm[4][DIM], sx[4][DIM];
    int tid = threadIdx.x;
    int n0 = blockIdx.x * 4;
#pragma unroll
    for (int r = 0; r < 4; r++) {
        sm[r][tid] = d_nm[(n0 + r) * DIM + tid];
        sx[r][tid] = x[(size_t)(n0 + r) * DIM + tid];
    }
    __syncthreads();
    float b = bs[tid];
    float a0 = b, a1 = b, a2 = b, a3 = b;
#pragma unroll 8
    for (int k = 0; k < DIM; k++) {
        float wl = Wl[k * DIM + tid];
        float wr = Wr[k * DIM + tid];
        a0 += sm[0][k] * wl + sx[0][k] * wr;
        a1 += sm[1][k] * wl + sx[1][k] * wr;
        a2 += sm[2][k] * wl + sx[2][k] * wr;
        a3 += sm[3][k] * wl + sx[3][k] * wr;
    }
    d_h[(n0 + 0) * DIM + tid] = a0 > 0.f ? a0 : __expf(a0) - 1.f;
    d_h[(n0 + 1) * DIM + tid] = a1 > 0.f ? a1 : __expf(a1) - 1.f;
    d_h[(n0 + 2) * DIM + tid] = a2 > 0.f ? a2 : __expf(a2) - 1.f;
    d_h[(n0 + 3) * DIM + tid] = a3 > 0.f ? a3 : __expf(a3) - 1.f;
}

// g = h@W_gat ; a_s, a_d reductions. 4 nodes/block, 512 threads.
__global__ void k_gat_lin(const float* __restrict__ Wg,
                          const float* __restrict__ att_s,
                          const float* __restrict__ att_d) {
    __shared__ float sh[4][DIM];
    __shared__ float rs[GDIM], rd[GDIM];
    int tid = threadIdx.x;
    int n0 = blockIdx.x * 4;
    if (tid < DIM) {
#pragma unroll
        for (int r = 0; r < 4; r++) sh[r][tid] = d_h[(n0 + r) * DIM + tid];
    }
    __syncthreads();
    float a0 = 0.f, a1 = 0.f, a2 = 0.f, a3 = 0.f;
#pragma unroll 8
    for (int k = 0; k < DIM; k++) {
        float w = Wg[k * GDIM + tid];
        a0 += sh[0][k] * w;
        a1 += sh[1][k] * w;
        a2 += sh[2][k] * w;
        a3 += sh[3][k] * w;
    }
    int head = tid >> 7;
    int c = tid & 127;
    float ws = att_s[head * DIM + c];
    float wd = att_d[head * DIM + c];
    float acc[4] = {a0, a1, a2, a3};
#pragma unroll
    for (int r = 0; r < 4; r++)
        d_g[(size_t)(n0 + r) * GDIM + tid] = acc[r];
#pragma unroll
    for (int r = 0; r < 4; r++) {
        rs[tid] = acc[r] * ws;
        rd[tid] = acc[r] * wd;
        __syncthreads();
        for (int off = 64; off > 0; off >>= 1) {
            if (c < off) { rs[tid] += rs[tid + off]; rd[tid] += rd[tid + off]; }
            __syncthreads();
        }
        if (c == 0) {
            d_as[(n0 + r) * NHEADS + head] = rs[tid];
            d_ad[(n0 + r) * NHEADS + head] = rd[tid];
        }
        __syncthreads();
    }
}

// GAT softmax-aggregate per dst node + fused mean-pool accumulate
__global__ void k_gat_agg(const int* __restrict__ batch,
                          const float* __restrict__ b_gat) {
    __shared__ float smax[NHEADS];
    int n = blockIdx.x;
    int tid = threadIdx.x;
    int beg = d_rowptr[n], end = d_rowptr[n + 1];

    if (tid < NHEADS) {
        float adh = d_ad[n * NHEADS + tid];
        float mx = -1e30f;
        for (int j = beg; j < end; j++) {
            int s = d_csrsrc[j];
            float v = d_as[s * NHEADS + tid] + adh;
            v = v > 0.f ? v : NEG_SLOPE * v;
            mx = fmaxf(mx, v);
        }
        smax[tid] = mx;
    }
    __syncthreads();
    float m0 = smax[0], m1 = smax[1], m2 = smax[2], m3 = smax[3];
    float ad0 = d_ad[n * NHEADS + 0], ad1 = d_ad[n * NHEADS + 1];
    float ad2 = d_ad[n * NHEADS + 2], ad3 = d_ad[n * NHEADS + 3];
    float acc0 = 0.f, acc1 = 0.f, acc2 = 0.f, acc3 = 0.f;
    float den0 = 0.f, den1 = 0.f, den2 = 0.f, den3 = 0.f;
    for (int j = beg; j < end; j++) {
        int s = d_csrsrc[j];
        const float* ap = d_as + s * NHEADS;
        float v0 = ap[0] + ad0; v0 = v0 > 0.f ? v0 : NEG_SLOPE * v0;
        float v1 = ap[1] + ad1; v1 = v1 > 0.f ? v1 : NEG_SLOPE * v1;
        float v2 = ap[2] + ad2; v2 = v2 > 0.f ? v2 : NEG_SLOPE * v2;
        float v3 = ap[3] + ad3; v3 = v3 > 0.f ? v3 : NEG_SLOPE * v3;
        float e0 = __expf(v0 - m0);
        float e1 = __expf(v1 - m1);
        float e2 = __expf(v2 - m2);
        float e3 = __expf(v3 - m3);
        den0 += e0; den1 += e1; den2 += e2; den3 += e3;
        const float* gs = d_g + (size_t)s * GDIM;
        acc0 += e0 * gs[tid];
        acc1 += e1 * gs[DIM + tid];
        acc2 += e2 * gs[2 * DIM + tid];
        acc3 += e3 * gs[3 * DIM + tid];
    }
    float o = acc0 / (den0 + 1e-16f) + acc1 / (den1 + 1e-16f)
            + acc2 / (den2 + 1e-16f) + acc3 / (den3 + 1e-16f);
    o = o * 0.25f + b_gat[tid];
    float hv = o > 0.f ? o : __expf(o) - 1.f;
    d_h2[n * DIM + tid] = hv;
    int b = batch[n];
    atomicAdd(&d_pool[b * DIM + tid], hv);
    if (tid == 0) atomicAdd(&d_pcnt[b], 1.f);
}

// wire / term heads: one warp per node
__global__ void k_heads(const float* __restrict__ Ww, const float* __restrict__ bw,
                        const float* __restrict__ Wt, const float* __restrict__ bt,
                        float* __restrict__ out) {
    int w = (blockIdx.x * blockDim.x + threadIdx.x) >> 5;
    if (w >= NN) return;
    int lane = threadIdx.x & 31;
    const float* Wv;
    float bias;
    if (w < NN - 10) { Wv = Ww; bias = bw[0]; }
    else             { Wv = Wt; bias = bt[0]; }
    float a = 0.f;
#pragma unroll
    for (int c = lane; c < DIM; c += 32) a += d_h2[w * DIM + c] * Wv[c];
#pragma unroll
    for (int off = 16; off > 0; off >>= 1)
        a += __shfl_xor_sync(0xffffffffu, a, off);
    if (lane == 0) out[w] = 1.f / (1.f + __expf(-(a + bias)));
}

__global__ void k_logits(const float* __restrict__ Wa, const float* __restrict__ ba,
                         float* __restrict__ out) {
    __shared__ float sp[DIM];
    int b = blockIdx.x;
    int tid = threadIdx.x;
    float cnt = fmaxf(d_pcnt[b], 1.f);
    sp[tid] = d_pool[b * DIM + tid] / cnt;
    __syncthreads();
    if (tid < NACT) {
        float a = ba[tid];
#pragma unroll 8
        for (int c = 0; c < DIM; c++) a += sp[c] * Wa[c * NACT + tid];
        out[NN + b * NACT + tid] = a;
    }
}

// ---------------- launch ----------------
extern "C" void kernel_launch(void* const* d_in, const int* in_sizes, int n_in,
                              void* d_out, int out_size) {
    const float* x     = (const float*)d_in[0];
    const int*   ei    = (const int*)d_in[1];
    const int*   batch = (const int*)d_in[2];
    const float* Wl   = (const float*)d_in[3];
    const float* Wr   = (const float*)d_in[4];
    const float* bs   = (const float*)d_in[5];
    const float* Wg   = (const float*)d_in[6];
    const float* ats  = (const float*)d_in[7];
    const float* atd  = (const float*)d_in[8];
    const float* bg   = (const float*)d_in[9];
    const float* Ww   = (const float*)d_in[10];
    const float* bw   = (const float*)d_in[11];
    const float* Wt   = (const float*)d_in[12];
    const float* bt   = (const float*)d_in[13];
    const float* Wa   = (const float*)d_in[14];
    const float* ba   = (const float*)d_in[15];
    float* out = (float*)d_out;

    k_zero<<<(NN + 255) / 256, 256>>>();
    k_count<<<EE / 256, 256>>>(ei);
    k_scan<<<1, 1024>>>();
    k_scatter<<<EE / 256, 256>>>(ei);
    k_sage_agg<<<NN, DIM>>>(x);
    k_sage_lin<<<NN / 4, DIM>>>(x, Wl, Wr, bs);
    k_gat_lin<<<NN / 4, GDIM>>>(Wg, ats, atd);
    k_gat_agg<<<NN, DIM>>>(batch, bg);
    k_heads<<<(NN * 32 + 127) / 128, 128>>>(Ww, bw, Wt, bt, out);
    k_logits<<<NB, DIM>>>(Wa, ba, out);
}